// round 9
// baseline (speedup 1.0000x reference)
#include <cuda_runtime.h>
#include <cuda_fp16.h>
#include <cstdint>

// ---------------- problem constants ----------------
#define BATCH   16384
#define SEQ     4
#define DIM     512
#define ROWS    (BATCH * SEQ)      // 65536
#define HEADS   8
#define GAMMA_F 0.4f
#define SCALE_F 0.044194173824159216f  // 512^-0.5

// scratch (allocation-free rule)
__device__ __half g_Qh [ROWS * DIM];          // fp16 Q
__device__ __half g_KVh[ROWS * 2 * DIM];      // fp16 KV
__device__ __half g_AOh[ROWS * DIM];          // fp16 attention output
// pre-transposed fp16 weights: Wt[n][k]
__device__ __half g_WtQh [DIM * DIM];
__device__ __half g_WtKVh[2 * DIM * DIM];
__device__ __half g_WtOh [DIM * DIM];

// ---------------- GEMM tiling ----------------
#define BM 128
#define BN 128
#define BK 64                       // 64 fp16 = 128B rows
#define NKT (DIM / BK)              // 8
// fused (fp32-act) kernel: 3-stage W (cp.async) + 2-stage X (STS)
#define FW_STAGE 16384
#define FX_STAGE 16384
#define F_SMEM (3 * FW_STAGE + 2 * FX_STAGE)   // 81920 -> 2 CTA/SM
// fp16-act kernel (mode 2): 3 stages of (W+X)
#define STAGES 3
#define STAGE_BYTES (FW_STAGE + FX_STAGE)
#define SMEM_BYTES (STAGES * STAGE_BYTES)      // 98304 -> 2 CTA/SM

// ---------------- helpers ----------------
__device__ __forceinline__ uint32_t smem_u32(const void* p) {
    uint32_t a;
    asm("{ .reg .u64 t; cvta.to.shared.u64 t, %1; cvt.u32.u64 %0, t; }"
        : "=r"(a) : "l"(p));
    return a;
}
__device__ __forceinline__ void cp16(uint32_t dst, const void* src) {
    asm volatile("cp.async.cg.shared.global [%0], [%1], 16;"
                 :: "r"(dst), "l"(src));
}
__device__ __forceinline__ void cp_commit() {
    asm volatile("cp.async.commit_group;");
}
template <int N>
__device__ __forceinline__ void cp_wait() {
    asm volatile("cp.async.wait_group %0;" :: "n"(N));
}
#define LDSM4(r0, r1, r2, r3, a) \
    asm volatile("ldmatrix.sync.aligned.m8n8.x4.shared.b16 {%0,%1,%2,%3}, [%4];" \
        : "=r"(r0), "=r"(r1), "=r"(r2), "=r"(r3) : "r"(a))

__device__ __forceinline__ void mma_f16(
    float c[4], uint32_t a0, uint32_t a1, uint32_t a2, uint32_t a3,
    uint32_t b0, uint32_t b1)
{
    asm volatile(
        "mma.sync.aligned.m16n8k16.row.col.f32.f16.f16.f32 "
        "{%0,%1,%2,%3}, {%4,%5,%6,%7}, {%8,%9}, {%0,%1,%2,%3};"
        : "+f"(c[0]), "+f"(c[1]), "+f"(c[2]), "+f"(c[3])
        : "r"(a0), "r"(a1), "r"(a2), "r"(a3), "r"(b0), "r"(b1));
}

// ---------------- prep: Wt[n][k] = fp16(W[k][n]) ----------------
__global__ void transpose_half(const float* __restrict__ W, int N, int sel)
{
    __half* Wt = (sel == 0) ? g_WtQh : (sel == 1) ? g_WtKVh : g_WtOh;
    __shared__ float t[32][33];
    int k0 = blockIdx.x * 32, n0 = blockIdx.y * 32;
    int tx = threadIdx.x, ty = threadIdx.y;
#pragma unroll
    for (int i = ty; i < 32; i += 8)
        t[i][tx] = W[(size_t)(k0 + i) * N + n0 + tx];
    __syncthreads();
#pragma unroll
    for (int i = ty; i < 32; i += 8)
        Wt[(size_t)(n0 + i) * DIM + k0 + tx] = __float2half_rn(t[tx][i]);
}

// shared MMA mainloop body (one k-tile): reads fp16 tiles at sW (W) and sX (Act)
__device__ __forceinline__ void mma_tile(
    uint32_t sW, uint32_t sX, int nb, int mb,
    int lx7, int arow, int agb, int brow, int bgb,
    float acc[2][8][4])
{
#pragma unroll
    for (int ks = 0; ks < 4; ks++) {
        uint32_t aw[2][4];
#pragma unroll
        for (int inf = 0; inf < 2; inf++) {
            int row = nb + inf * 16 + arow;
            uint32_t ad = sW + row * 128
                        + (uint32_t)(((2 * ks + agb) ^ lx7) << 4);
            LDSM4(aw[inf][0], aw[inf][1], aw[inf][2], aw[inf][3], ad);
        }
        uint32_t bx[8][2];
#pragma unroll
        for (int jp = 0; jp < 4; jp++) {
            int row = mb + jp * 16 + brow;
            uint32_t ad = sX + row * 128
                        + (uint32_t)(((2 * ks + bgb) ^ lx7) << 4);
            uint32_t r0, r1, r2, r3;
            LDSM4(r0, r1, r2, r3, ad);
            bx[2 * jp][0]     = r0;
            bx[2 * jp][1]     = r1;
            bx[2 * jp + 1][0] = r2;
            bx[2 * jp + 1][1] = r3;
        }
#pragma unroll
        for (int inf = 0; inf < 2; inf++)
#pragma unroll
            for (int jm = 0; jm < 8; jm++)
                mma_f16(acc[inf][jm],
                        aw[inf][0], aw[inf][1], aw[inf][2], aw[inf][3],
                        bx[jm][0], bx[jm][1]);
    }
}

// shared epilogue: acc -> smem transpose -> fp16 global (bias added)
__device__ __forceinline__ void epilogue_h(
    float* Cs, __half* Co, const float* bias, int ldN,
    int m0, int n0, int nb, int mb, int tid, int l,
    float acc[2][8][4])
{
    const int gq = l >> 2, tq = l & 3;
#pragma unroll
    for (int inf = 0; inf < 2; inf++) {
        int nn = nb + inf * 16 + gq;
#pragma unroll
        for (int jm = 0; jm < 8; jm++) {
            int mm = mb + jm * 8 + 2 * tq;
            Cs[mm * 132 + nn]           = acc[inf][jm][0];
            Cs[(mm + 1) * 132 + nn]     = acc[inf][jm][1];
            Cs[mm * 132 + nn + 8]       = acc[inf][jm][2];
            Cs[(mm + 1) * 132 + nn + 8] = acc[inf][jm][3];
        }
    }
    __syncthreads();
#pragma unroll
    for (int it = 0; it < 8; it++) {
        int idx = tid + it * 256;
        int r = idx >> 4, c = (idx & 15) * 8;
        float4 v0 = *(float4*)&Cs[r * 132 + c];
        float4 v1 = *(float4*)&Cs[r * 132 + c + 4];
        const float* bp = &bias[n0 + c];
        __half2 h[4];
        h[0] = __floats2half2_rn(v0.x + bp[0], v0.y + bp[1]);
        h[1] = __floats2half2_rn(v0.z + bp[2], v0.w + bp[3]);
        h[2] = __floats2half2_rn(v1.x + bp[4], v1.y + bp[5]);
        h[3] = __floats2half2_rn(v1.z + bp[6], v1.w + bp[7]);
        *(uint4*)&Co[(size_t)(m0 + r) * ldN + n0 + c] = *(uint4*)h;
    }
}

// ---------------- fused Q+KV GEMM: fp32 Act in, fp16 out ----------------
// grid.x: 0..3 -> Q n-tiles (x @ WtQ), 4..11 -> KV n-tiles (ctx @ WtKV)
__global__ __launch_bounds__(256, 2) void gemm_fused(
    const float* __restrict__ x, const float* __restrict__ ctx,
    const float* __restrict__ bq, const float* __restrict__ bkv)
{
    extern __shared__ float smf[];
    const uint32_t smb = smem_u32(smf);

    const int nt = blockIdx.x;
    const int isKV = (nt >= 4);
    const float* Act   = isKV ? ctx : x;
    const __half* Wt   = isKV ? g_WtKVh : g_WtQh;
    const float* bias  = isKV ? bkv : bq;
    __half* Co         = isKV ? g_KVh : g_Qh;
    const int ldN      = isKV ? 2 * DIM : DIM;
    const int n0       = (isKV ? nt - 4 : nt) * BN;
    const int m0       = blockIdx.y * BM;

    const int tid = threadIdx.x;
    const int wid = tid >> 5;
    const int l   = tid & 31;
    const int nb = (wid & 3) * 32, mb = (wid >> 2) * 64;

    const int lx7  = l & 7;
    const int arow = (l & 7) + ((l >> 3) & 1) * 8;
    const int agb  = l >> 4;
    const int brow = (l & 7) + ((l >> 4) << 3);
    const int bgb  = (l >> 3) & 1;

    // stage addresses
    uint32_t sWst[3], sXst[2];
#pragma unroll
    for (int s = 0; s < 3; s++) sWst[s] = smb + s * FW_STAGE;
#pragma unroll
    for (int s = 0; s < 2; s++) sXst[s] = smb + 3 * FW_STAGE + s * FX_STAGE;

    // per-thread X copy coords: 8 granules of 4 fp32 (r: row, c: granule)
    // STS target: halves row r (128B), 8B chunk at col c*8, swizzled
    float4 xr[8];

    float acc[2][8][4];
#pragma unroll
    for (int i = 0; i < 2; i++)
#pragma unroll
        for (int j = 0; j < 8; j++)
#pragma unroll
            for (int c = 0; c < 4; c++) acc[i][j][c] = 0.0f;

    // -- prologue --
    // W stages 0,1 via cp.async
#pragma unroll
    for (int s = 0; s < 2; s++) {
#pragma unroll
        for (int j = 0; j < 4; j++) {
            int g = tid + j * 256;
            int r = g >> 3, c = g & 7;
            uint32_t off = (uint32_t)(r * 128 + ((c ^ (r & 7)) << 4));
            cp16(sWst[s] + off, &Wt[(size_t)(n0 + r) * DIM + s * BK + c * 8]);
        }
        cp_commit();
    }
    // X tile 0: LDG fp32 -> cvt -> STS stage 0
#pragma unroll
    for (int j = 0; j < 8; j++) {
        int g = tid + j * 256;
        int r = g >> 4, c = g & 15;
        xr[j] = *(const float4*)&Act[(size_t)(m0 + r) * DIM + c * 4];
    }
#pragma unroll
    for (int j = 0; j < 8; j++) {
        int g = tid + j * 256;
        int r = g >> 4, c = g & 15;
        __half2 h[2];
        h[0] = __floats2half2_rn(xr[j].x, xr[j].y);
        h[1] = __floats2half2_rn(xr[j].z, xr[j].w);
        uint32_t ad = sXst[0] + (uint32_t)(r * 128 + (((c >> 1) ^ (r & 7)) << 4) + (c & 1) * 8);
        asm volatile("st.shared.v2.b32 [%0], {%1,%2};"
                     :: "r"(ad), "r"(*(uint32_t*)&h[0]), "r"(*(uint32_t*)&h[1]) : "memory");
    }

#pragma unroll
    for (int t = 0; t < NKT; t++) {
        cp_wait<1>();          // W tile t landed
        __syncthreads();       // X tile t STS visible; stage reuse safe

        const bool haveX = (t + 1 < NKT);
        if (haveX) {           // prefetch X tile t+1 into regs (latency hidden by MMA)
#pragma unroll
            for (int j = 0; j < 8; j++) {
                int g = tid + j * 256;
                int r = g >> 4, c = g & 15;
                xr[j] = *(const float4*)&Act[(size_t)(m0 + r) * DIM + (t + 1) * BK + c * 4];
            }
        }
        if (t + 2 < NKT) {     // W tile t+2 via cp.async
#pragma unroll
            for (int j = 0; j < 4; j++) {
                int g = tid + j * 256;
                int r = g >> 3, c = g & 7;
                uint32_t off = (uint32_t)(r * 128 + ((c ^ (r & 7)) << 4));
                cp16(sWst[(t + 2) % 3] + off,
                     &Wt[(size_t)(n0 + r) * DIM + (t + 2) * BK + c * 8]);
            }
        }
        cp_commit();

        mma_tile(sWst[t % 3], sXst[t & 1], nb, mb,
                 lx7, arow, agb, brow, bgb, acc);

        if (haveX) {           // cvt + STS X tile t+1 into the other stage
#pragma unroll
            for (int j = 0; j < 8; j++) {
                int g = tid + j * 256;
                int r = g >> 4, c = g & 15;
                __half2 h[2];
                h[0] = __floats2half2_rn(xr[j].x, xr[j].y);
                h[1] = __floats2half2_rn(xr[j].z, xr[j].w);
                uint32_t ad = sXst[(t + 1) & 1]
                            + (uint32_t)(r * 128 + (((c >> 1) ^ (r & 7)) << 4) + (c & 1) * 8);
                asm volatile("st.shared.v2.b32 [%0], {%1,%2};"
                             :: "r"(ad), "r"(*(uint32_t*)&h[0]), "r"(*(uint32_t*)&h[1]) : "memory");
            }
        }
    }

    cp_wait<0>();
    __syncthreads();
    epilogue_h(smf, Co, bias, ldN, m0, n0, nb, mb, tid, l, acc);
}

// ---------------- O GEMM: fp16 AO in (cp.async), fp32 out ----------------
__global__ __launch_bounds__(256, 2) void gemm_mma(
    const float* __restrict__ bias, float* __restrict__ Cext, int ldN)
{
    extern __shared__ float smf[];
    const uint32_t smb = smem_u32(smf);

    const __half* Act = g_AOh;
    const __half* Wt  = g_WtOh;

    const int tid = threadIdx.x;
    const int wid = tid >> 5;
    const int l   = tid & 31;
    const int nb = (wid & 3) * 32, mb = (wid >> 2) * 64;
    const int m0 = blockIdx.y * BM, n0 = blockIdx.x * BN;

    const int lx7  = l & 7;
    const int arow = (l & 7) + ((l >> 3) & 1) * 8;
    const int agb  = l >> 4;
    const int brow = (l & 7) + ((l >> 4) << 3);
    const int bgb  = (l >> 3) & 1;

    float acc[2][8][4];
#pragma unroll
    for (int i = 0; i < 2; i++)
#pragma unroll
        for (int j = 0; j < 8; j++)
#pragma unroll
            for (int c = 0; c < 4; c++) acc[i][j][c] = 0.0f;

    auto issue = [&](int t) {
        uint32_t sW = smb + (t % STAGES) * STAGE_BYTES;
        uint32_t sX = sW + FW_STAGE;
#pragma unroll
        for (int j = 0; j < 4; j++) {
            int g = tid + j * 256;
            int r = g >> 3, c = g & 7;
            uint32_t off = (uint32_t)(r * 128 + ((c ^ (r & 7)) << 4));
            cp16(sW + off, &Wt[(size_t)(n0 + r) * DIM + t * BK + c * 8]);
            cp16(sX + off, &Act[(size_t)(m0 + r) * DIM + t * BK + c * 8]);
        }
    };

    issue(0); cp_commit();
    issue(1); cp_commit();

    for (int kt = 0; kt < NKT; kt++) {
        cp_wait<STAGES - 2>();
        __syncthreads();
        if (kt + STAGES - 1 < NKT) issue(kt + STAGES - 1);
        cp_commit();
        uint32_t sW = smb + (kt % STAGES) * STAGE_BYTES;
        mma_tile(sW, sW + FW_STAGE, nb, mb, lx7, arow, agb, brow, bgb, acc);
    }

    cp_wait<0>();
    __syncthreads();
    float* Cs = smf;
    const int gq = l >> 2, tq = l & 3;
#pragma unroll
    for (int inf = 0; inf < 2; inf++) {
        int nn = nb + inf * 16 + gq;
#pragma unroll
        for (int jm = 0; jm < 8; jm++) {
            int mm = mb + jm * 8 + 2 * tq;
            Cs[mm * 132 + nn]           = acc[inf][jm][0];
            Cs[(mm + 1) * 132 + nn]     = acc[inf][jm][1];
            Cs[mm * 132 + nn + 8]       = acc[inf][jm][2];
            Cs[(mm + 1) * 132 + nn + 8] = acc[inf][jm][3];
        }
    }
    __syncthreads();
#pragma unroll
    for (int it = 0; it < 16; it++) {
        int idx = tid + it * 256;
        int r = idx >> 5, c = (idx & 31) * 4;
        float4 v = *(float4*)&Cs[r * 132 + c];
        v.x += bias[n0 + c];
        v.y += bias[n0 + c + 1];
        v.z += bias[n0 + c + 2];
        v.w += bias[n0 + c + 3];
        *(float4*)&Cext[(size_t)(m0 + r) * ldN + n0 + c] = v;
    }
}

// ---------------- attention: one warp per (batch, head), fp16 in/out ----------------
__global__ __launch_bounds__(256) void attn_kernel()
{
    int gwarp = blockIdx.x * 8 + (threadIdx.x >> 5);
    int lane = threadIdx.x & 31;
    if (gwarp >= BATCH * HEADS) return;
    int b = gwarp >> 3;
    int h = gwarp & 7;

    const __half* qb  = g_Qh  + (size_t)b * SEQ * DIM       + h * 64;
    const __half* kvb = g_KVh + (size_t)b * SEQ * (2 * DIM) + h * 64;

    float2 q[4], k[4], v[4];
#pragma unroll
    for (int i = 0; i < 4; i++) {
        q[i] = __half22float2(*(const __half2*)&qb[i * DIM + 2 * lane]);
        k[i] = __half22float2(*(const __half2*)&kvb[i * (2 * DIM) + 2 * lane]);
        v[i] = __half22float2(*(const __half2*)&kvb[i * (2 * DIM) + DIM + 2 * lane]);
    }

    float s[4][4];
#pragma unroll
    for (int i = 0; i < 4; i++) {
#pragma unroll
        for (int j = 0; j < 4; j++) {
            float p = q[i].x * k[j].x + q[i].y * k[j].y;
#pragma unroll
            for (int o = 16; o > 0; o >>= 1)
                p += __shfl_xor_sync(0xFFFFFFFFu, p, o);
            s[i][j] = p * SCALE_F;
        }
    }

#pragma unroll
    for (int i = 0; i < 4; i++) {
        int jm = 3 - i;                         // masked pair (dist = sqrt2)
        s[i][jm] = -(float)(jm + 1) * GAMMA_F;  // finite bias, stays in denominator

        float mx = fmaxf(fmaxf(s[i][0], s[i][1]), fmaxf(s[i][2], s[i][3]));
        float e[4], sum = 0.0f;
#pragma unroll
        for (int j = 0; j < 4; j++) { e[j] = expf(s[i][j] - mx); sum += e[j]; }
        float inv = 1.0f / sum;
        float p[4];
#pragma unroll
        for (int j = 0; j < 4; j++) p[j] = e[j] * inv;
        p[jm] = 0.0f;                           // post-softmax mask

        float o0 = 0.0f, o1 = 0.0f;
#pragma unroll
        for (int j = 0; j < 4; j++) { o0 += p[j] * v[j].x; o1 += p[j] * v[j].y; }

        __half2* dst = (__half2*)(g_AOh + (size_t)(b * SEQ + i) * DIM + h * 64 + 2 * lane);
        *dst = __floats2half2_rn(o0, o1);
    }
}

// ---------------- launch ----------------
extern "C" void kernel_launch(void* const* d_in, const int* in_sizes, int n_in,
                              void* d_out, int out_size)
{
    const float* x   = (const float*)d_in[0];
    const float* ctx = (const float*)d_in[1];
    const float* Wq  = (const float*)d_in[2];
    const float* bq  = (const float*)d_in[3];
    const float* Wkv = (const float*)d_in[4];
    const float* bkv = (const float*)d_in[5];
    const float* Wo  = (const float*)d_in[6];
    const float* bo  = (const float*)d_in[7];
    float* out = (float*)d_out;

    cudaFuncSetAttribute(gemm_fused, cudaFuncAttributeMaxDynamicSharedMemorySize, F_SMEM);
    cudaFuncSetAttribute(gemm_mma, cudaFuncAttributeMaxDynamicSharedMemorySize, SMEM_BYTES);

    dim3 tb(32, 8);
    transpose_half<<<dim3(DIM / 32, DIM / 32), tb>>>(Wq, DIM, 0);
    transpose_half<<<dim3(DIM / 32, 2 * DIM / 32), tb>>>(Wkv, 2 * DIM, 1);
    transpose_half<<<dim3(DIM / 32, DIM / 32), tb>>>(Wo, DIM, 2);

    // Q and KV in one launch: fp32 x/ctx in, fp16 Q/KV out
    gemm_fused<<<dim3(12, ROWS / BM), 256, F_SMEM>>>(x, ctx, bq, bkv);
    // attention (fp16 in/out)
    attn_kernel<<<BATCH * HEADS / 8, 256>>>();
    // out = AO @ Wo + bo (fp32 out)
    gemm_mma<<<dim3(DIM / BN, ROWS / BM), 256, SMEM_BYTES>>>(bo, out, DIM);
}

// round 10
// speedup vs baseline: 1.0955x; 1.0955x over previous
#include <cuda_runtime.h>
#include <cuda_fp16.h>
#include <cstdint>

// ---------------- problem constants ----------------
#define BATCH   16384
#define SEQ     4
#define DIM     512
#define ROWS    (BATCH * SEQ)      // 65536
#define HEADS   8
#define GAMMA_F 0.4f
#define SCALE_F 0.044194173824159216f  // 512^-0.5

// scratch (allocation-free rule)
__device__ __half g_Qh [ROWS * DIM];          // fp16 Q
__device__ __half g_KVh[ROWS * 2 * DIM];      // fp16 KV
__device__ __half g_AOh[ROWS * DIM];          // fp16 attention output
__device__ __half g_Xh [ROWS * DIM];          // fp16 x
__device__ __half g_Ch [ROWS * DIM];          // fp16 context
// pre-transposed fp16 weights: Wt[n][k]
__device__ __half g_WtQh [DIM * DIM];
__device__ __half g_WtKVh[2 * DIM * DIM];
__device__ __half g_WtOh [DIM * DIM];

// ---------------- GEMM tiling ----------------
#define BM 128
#define BN 128
#define BK 64                       // 64 fp16 = 128B rows
#define NKT (DIM / BK)              // 8
#define STAGES 3
#define W_STAGE 16384
#define X_STAGE 16384
#define STAGE_BYTES (W_STAGE + X_STAGE)
#define SMEM_BYTES (STAGES * STAGE_BYTES)   // 98304 -> 2 CTA/SM

// ---------------- helpers ----------------
__device__ __forceinline__ uint32_t smem_u32(const void* p) {
    uint32_t a;
    asm("{ .reg .u64 t; cvta.to.shared.u64 t, %1; cvt.u32.u64 %0, t; }"
        : "=r"(a) : "l"(p));
    return a;
}
__device__ __forceinline__ void cp16(uint32_t dst, const void* src) {
    asm volatile("cp.async.cg.shared.global [%0], [%1], 16;"
                 :: "r"(dst), "l"(src));
}
__device__ __forceinline__ void cp_commit() {
    asm volatile("cp.async.commit_group;");
}
template <int N>
__device__ __forceinline__ void cp_wait() {
    asm volatile("cp.async.wait_group %0;" :: "n"(N));
}
#define LDSM4(r0, r1, r2, r3, a) \
    asm volatile("ldmatrix.sync.aligned.m8n8.x4.shared.b16 {%0,%1,%2,%3}, [%4];" \
        : "=r"(r0), "=r"(r1), "=r"(r2), "=r"(r3) : "r"(a))

__device__ __forceinline__ void mma_f16(
    float c[4], uint32_t a0, uint32_t a1, uint32_t a2, uint32_t a3,
    uint32_t b0, uint32_t b1)
{
    asm volatile(
        "mma.sync.aligned.m16n8k16.row.col.f32.f16.f16.f32 "
        "{%0,%1,%2,%3}, {%4,%5,%6,%7}, {%8,%9}, {%0,%1,%2,%3};"
        : "+f"(c[0]), "+f"(c[1]), "+f"(c[2]), "+f"(c[3])
        : "r"(a0), "r"(a1), "r"(a2), "r"(a3), "r"(b0), "r"(b1));
}

// ---------------- prep: all 3 weights transposed+rounded in ONE launch ----------------
// blockIdx.y: [0,16) -> Wq, [16,48) -> Wkv, [48,64) -> Wo
__global__ void transpose_all(const float* __restrict__ Wq,
                              const float* __restrict__ Wkv,
                              const float* __restrict__ Wo)
{
    int y = blockIdx.y;
    const float* W;
    __half* Wt;
    int N, n0;
    if (y < 16)      { W = Wq;  Wt = g_WtQh;  N = DIM;     n0 = y * 32; }
    else if (y < 48) { W = Wkv; Wt = g_WtKVh; N = 2 * DIM; n0 = (y - 16) * 32; }
    else             { W = Wo;  Wt = g_WtOh;  N = DIM;     n0 = (y - 48) * 32; }

    __shared__ float t[32][33];
    int k0 = blockIdx.x * 32;
    int tx = threadIdx.x, ty = threadIdx.y;
#pragma unroll
    for (int i = ty; i < 32; i += 8)
        t[i][tx] = W[(size_t)(k0 + i) * N + n0 + tx];
    __syncthreads();
#pragma unroll
    for (int i = ty; i < 32; i += 8)
        Wt[(size_t)(n0 + i) * DIM + k0 + tx] = __float2half_rn(t[tx][i]);
}

// ---------------- prep: x AND ctx -> fp16 in ONE launch ----------------
#define TOH_BLOCKS (ROWS * DIM / 4 / 256)     // 32768 per tensor
__global__ void to_half2(const float* __restrict__ x, const float* __restrict__ ctx)
{
    int bid = blockIdx.x;
    const float* src;
    __half* dst;
    int base;
    if (bid < TOH_BLOCKS) { src = x;   dst = g_Xh; base = bid; }
    else                  { src = ctx; dst = g_Ch; base = bid - TOH_BLOCKS; }
    int i = (base * 256 + threadIdx.x) * 4;
    float4 v = *(const float4*)&src[i];
    *(__half2*)&dst[i]     = __floats2half2_rn(v.x, v.y);
    *(__half2*)&dst[i + 2] = __floats2half2_rn(v.z, v.w);
}

// shared MMA mainloop body (one k-tile)
__device__ __forceinline__ void mma_tile(
    uint32_t sW, uint32_t sX, int nb, int mb,
    int lx7, int arow, int agb, int brow, int bgb,
    float acc[2][8][4])
{
#pragma unroll
    for (int ks = 0; ks < 4; ks++) {
        uint32_t aw[2][4];
#pragma unroll
        for (int inf = 0; inf < 2; inf++) {
            int row = nb + inf * 16 + arow;
            uint32_t ad = sW + row * 128
                        + (uint32_t)(((2 * ks + agb) ^ lx7) << 4);
            LDSM4(aw[inf][0], aw[inf][1], aw[inf][2], aw[inf][3], ad);
        }
        uint32_t bx[8][2];
#pragma unroll
        for (int jp = 0; jp < 4; jp++) {
            int row = mb + jp * 16 + brow;
            uint32_t ad = sX + row * 128
                        + (uint32_t)(((2 * ks + bgb) ^ lx7) << 4);
            uint32_t r0, r1, r2, r3;
            LDSM4(r0, r1, r2, r3, ad);
            bx[2 * jp][0]     = r0;
            bx[2 * jp][1]     = r1;
            bx[2 * jp + 1][0] = r2;
            bx[2 * jp + 1][1] = r3;
        }
#pragma unroll
        for (int inf = 0; inf < 2; inf++)
#pragma unroll
            for (int jm = 0; jm < 8; jm++)
                mma_f16(acc[inf][jm],
                        aw[inf][0], aw[inf][1], aw[inf][2], aw[inf][3],
                        bx[jm][0], bx[jm][1]);
    }
}

// ---------------- fused Q+KV GEMM (fp16 in, fp16 out) ----------------
// grid.x: 0..3 -> Q n-tiles (Xh @ WtQ), 4..11 -> KV n-tiles (Ch @ WtKV)
__global__ __launch_bounds__(256, 2) void gemm_qkv(
    const float* __restrict__ bq, const float* __restrict__ bkv)
{
    extern __shared__ float smf[];
    const uint32_t smb = smem_u32(smf);

    const int nt = blockIdx.x;
    const int isKV = (nt >= 4);
    const __half* Act  = isKV ? g_Ch : g_Xh;
    const __half* Wt   = isKV ? g_WtKVh : g_WtQh;
    const float* bias  = isKV ? bkv : bq;
    __half* Co         = isKV ? g_KVh : g_Qh;
    const int ldN      = isKV ? 2 * DIM : DIM;
    const int n0       = (isKV ? nt - 4 : nt) * BN;
    const int m0       = blockIdx.y * BM;

    const int tid = threadIdx.x;
    const int wid = tid >> 5;
    const int l   = tid & 31;
    const int nb = (wid & 3) * 32, mb = (wid >> 2) * 64;

    const int lx7  = l & 7;
    const int arow = (l & 7) + ((l >> 3) & 1) * 8;
    const int agb  = l >> 4;
    const int brow = (l & 7) + ((l >> 4) << 3);
    const int bgb  = (l >> 3) & 1;

    float acc[2][8][4];
#pragma unroll
    for (int i = 0; i < 2; i++)
#pragma unroll
        for (int j = 0; j < 8; j++)
#pragma unroll
            for (int c = 0; c < 4; c++) acc[i][j][c] = 0.0f;

    auto issue = [&](int t) {
        uint32_t sW = smb + (t % STAGES) * STAGE_BYTES;
        uint32_t sX = sW + W_STAGE;
#pragma unroll
        for (int j = 0; j < 4; j++) {
            int g = tid + j * 256;
            int r = g >> 3, c = g & 7;
            uint32_t off = (uint32_t)(r * 128 + ((c ^ (r & 7)) << 4));
            cp16(sW + off, &Wt[(size_t)(n0 + r) * DIM + t * BK + c * 8]);
            cp16(sX + off, &Act[(size_t)(m0 + r) * DIM + t * BK + c * 8]);
        }
    };

    issue(0); cp_commit();
    issue(1); cp_commit();

    for (int kt = 0; kt < NKT; kt++) {
        cp_wait<STAGES - 2>();
        __syncthreads();
        if (kt + STAGES - 1 < NKT) issue(kt + STAGES - 1);
        cp_commit();
        uint32_t sW = smb + (kt % STAGES) * STAGE_BYTES;
        mma_tile(sW, sW + W_STAGE, nb, mb, lx7, arow, agb, brow, bgb, acc);
    }

    // epilogue: transpose via smem, bias, fp16 coalesced store
    cp_wait<0>();
    __syncthreads();
    float* Cs = smf;
    const int gq = l >> 2, tq = l & 3;
#pragma unroll
    for (int inf = 0; inf < 2; inf++) {
        int nn = nb + inf * 16 + gq;
#pragma unroll
        for (int jm = 0; jm < 8; jm++) {
            int mm = mb + jm * 8 + 2 * tq;
            Cs[mm * 132 + nn]           = acc[inf][jm][0];
            Cs[(mm + 1) * 132 + nn]     = acc[inf][jm][1];
            Cs[mm * 132 + nn + 8]       = acc[inf][jm][2];
            Cs[(mm + 1) * 132 + nn + 8] = acc[inf][jm][3];
        }
    }
    __syncthreads();
#pragma unroll
    for (int it = 0; it < 8; it++) {
        int idx = tid + it * 256;
        int r = idx >> 4, c = (idx & 15) * 8;
        float4 v0 = *(float4*)&Cs[r * 132 + c];
        float4 v1 = *(float4*)&Cs[r * 132 + c + 4];
        const float* bp = &bias[n0 + c];
        __half2 h[4];
        h[0] = __floats2half2_rn(v0.x + bp[0], v0.y + bp[1]);
        h[1] = __floats2half2_rn(v0.z + bp[2], v0.w + bp[3]);
        h[2] = __floats2half2_rn(v1.x + bp[4], v1.y + bp[5]);
        h[3] = __floats2half2_rn(v1.z + bp[6], v1.w + bp[7]);
        *(uint4*)&Co[(size_t)(m0 + r) * ldN + n0 + c] = *(uint4*)h;
    }
}

// ---------------- O GEMM: fp16 AO in, fp32 out ----------------
__global__ __launch_bounds__(256, 2) void gemm_o(
    const float* __restrict__ bias, float* __restrict__ Cext, int ldN)
{
    extern __shared__ float smf[];
    const uint32_t smb = smem_u32(smf);

    const __half* Act = g_AOh;
    const __half* Wt  = g_WtOh;

    const int tid = threadIdx.x;
    const int wid = tid >> 5;
    const int l   = tid & 31;
    const int nb = (wid & 3) * 32, mb = (wid >> 2) * 64;
    const int m0 = blockIdx.y * BM, n0 = blockIdx.x * BN;

    const int lx7  = l & 7;
    const int arow = (l & 7) + ((l >> 3) & 1) * 8;
    const int agb  = l >> 4;
    const int brow = (l & 7) + ((l >> 4) << 3);
    const int bgb  = (l >> 3) & 1;

    float acc[2][8][4];
#pragma unroll
    for (int i = 0; i < 2; i++)
#pragma unroll
        for (int j = 0; j < 8; j++)
#pragma unroll
            for (int c = 0; c < 4; c++) acc[i][j][c] = 0.0f;

    auto issue = [&](int t) {
        uint32_t sW = smb + (t % STAGES) * STAGE_BYTES;
        uint32_t sX = sW + W_STAGE;
#pragma unroll
        for (int j = 0; j < 4; j++) {
            int g = tid + j * 256;
            int r = g >> 3, c = g & 7;
            uint32_t off = (uint32_t)(r * 128 + ((c ^ (r & 7)) << 4));
            cp16(sW + off, &Wt[(size_t)(n0 + r) * DIM + t * BK + c * 8]);
            cp16(sX + off, &Act[(size_t)(m0 + r) * DIM + t * BK + c * 8]);
        }
    };

    issue(0); cp_commit();
    issue(1); cp_commit();

    for (int kt = 0; kt < NKT; kt++) {
        cp_wait<STAGES - 2>();
        __syncthreads();
        if (kt + STAGES - 1 < NKT) issue(kt + STAGES - 1);
        cp_commit();
        uint32_t sW = smb + (kt % STAGES) * STAGE_BYTES;
        mma_tile(sW, sW + W_STAGE, nb, mb, lx7, arow, agb, brow, bgb, acc);
    }

    cp_wait<0>();
    __syncthreads();
    float* Cs = smf;
    const int gq = l >> 2, tq = l & 3;
#pragma unroll
    for (int inf = 0; inf < 2; inf++) {
        int nn = nb + inf * 16 + gq;
#pragma unroll
        for (int jm = 0; jm < 8; jm++) {
            int mm = mb + jm * 8 + 2 * tq;
            Cs[mm * 132 + nn]           = acc[inf][jm][0];
            Cs[(mm + 1) * 132 + nn]     = acc[inf][jm][1];
            Cs[mm * 132 + nn + 8]       = acc[inf][jm][2];
            Cs[(mm + 1) * 132 + nn + 8] = acc[inf][jm][3];
        }
    }
    __syncthreads();
#pragma unroll
    for (int it = 0; it < 16; it++) {
        int idx = tid + it * 256;
        int r = idx >> 5, c = (idx & 31) * 4;
        float4 v = *(float4*)&Cs[r * 132 + c];
        v.x += bias[n0 + c];
        v.y += bias[n0 + c + 1];
        v.z += bias[n0 + c + 2];
        v.w += bias[n0 + c + 3];
        *(float4*)&Cext[(size_t)(m0 + r) * ldN + n0 + c] = v;
    }
}

// ---------------- attention: one warp per (batch, head), fp16 in/out ----------------
__global__ __launch_bounds__(256) void attn_kernel()
{
    int gwarp = blockIdx.x * 8 + (threadIdx.x >> 5);
    int lane = threadIdx.x & 31;
    if (gwarp >= BATCH * HEADS) return;
    int b = gwarp >> 3;
    int h = gwarp & 7;

    const __half* qb  = g_Qh  + (size_t)b * SEQ * DIM       + h * 64;
    const __half* kvb = g_KVh + (size_t)b * SEQ * (2 * DIM) + h * 64;

    float2 q[4], k[4], v[4];
#pragma unroll
    for (int i = 0; i < 4; i++) {
        q[i] = __half22float2(*(const __half2*)&qb[i * DIM + 2 * lane]);
        k[i] = __half22float2(*(const __half2*)&kvb[i * (2 * DIM) + 2 * lane]);
        v[i] = __half22float2(*(const __half2*)&kvb[i * (2 * DIM) + DIM + 2 * lane]);
    }

    float s[4][4];
#pragma unroll
    for (int i = 0; i < 4; i++) {
#pragma unroll
        for (int j = 0; j < 4; j++) {
            float p = q[i].x * k[j].x + q[i].y * k[j].y;
#pragma unroll
            for (int o = 16; o > 0; o >>= 1)
                p += __shfl_xor_sync(0xFFFFFFFFu, p, o);
            s[i][j] = p * SCALE_F;
        }
    }

#pragma unroll
    for (int i = 0; i < 4; i++) {
        int jm = 3 - i;                         // masked pair (dist = sqrt2)
        s[i][jm] = -(float)(jm + 1) * GAMMA_F;  // finite bias, stays in denominator

        float mx = fmaxf(fmaxf(s[i][0], s[i][1]), fmaxf(s[i][2], s[i][3]));
        float e[4], sum = 0.0f;
#pragma unroll
        for (int j = 0; j < 4; j++) { e[j] = expf(s[i][j] - mx); sum += e[j]; }
        float inv = 1.0f / sum;
        float p[4];
#pragma unroll
        for (int j = 0; j < 4; j++) p[j] = e[j] * inv;
        p[jm] = 0.0f;                           // post-softmax mask

        float o0 = 0.0f, o1 = 0.0f;
#pragma unroll
        for (int j = 0; j < 4; j++) { o0 += p[j] * v[j].x; o1 += p[j] * v[j].y; }

        __half2* dst = (__half2*)(g_AOh + (size_t)(b * SEQ + i) * DIM + h * 64 + 2 * lane);
        *dst = __floats2half2_rn(o0, o1);
    }
}

// ---------------- launch ----------------
extern "C" void kernel_launch(void* const* d_in, const int* in_sizes, int n_in,
                              void* d_out, int out_size)
{
    const float* x   = (const float*)d_in[0];
    const float* ctx = (const float*)d_in[1];
    const float* Wq  = (const float*)d_in[2];
    const float* bq  = (const float*)d_in[3];
    const float* Wkv = (const float*)d_in[4];
    const float* bkv = (const float*)d_in[5];
    const float* Wo  = (const float*)d_in[6];
    const float* bo  = (const float*)d_in[7];
    float* out = (float*)d_out;

    cudaFuncSetAttribute(gemm_qkv, cudaFuncAttributeMaxDynamicSharedMemorySize, SMEM_BYTES);
    cudaFuncSetAttribute(gemm_o, cudaFuncAttributeMaxDynamicSharedMemorySize, SMEM_BYTES);

    // prep: all weights in one launch; both activations in one launch
    transpose_all<<<dim3(16, 64), dim3(32, 8)>>>(Wq, Wkv, Wo);
    to_half2<<<2 * TOH_BLOCKS, 256>>>(x, ctx);

    // Q and KV in one launch (fp16 in/out)
    gemm_qkv<<<dim3(12, ROWS / BM), 256, SMEM_BYTES>>>(bq, bkv);
    // attention (fp16 in/out)
    attn_kernel<<<BATCH * HEADS / 8, 256>>>();
    // out = AO @ Wo + bo (fp32 out)
    gemm_o<<<dim3(DIM / BN, ROWS / BM), 256, SMEM_BYTES>>>(bo, out, DIM);
}

// round 11
// speedup vs baseline: 1.1527x; 1.0522x over previous
#include <cuda_runtime.h>
#include <cuda_fp16.h>
#include <cstdint>

// ---------------- problem constants ----------------
#define BATCH   16384
#define SEQ     4
#define DIM     512
#define ROWS    (BATCH * SEQ)      // 65536
#define HEADS   8
#define GAMMA_F 0.4f
#define SCALE_F 0.044194173824159216f  // 512^-0.5

// scratch (allocation-free rule)
__device__ __half g_Qh [ROWS * DIM];          // fp16 Q
__device__ __half g_KVh[ROWS * 2 * DIM];      // fp16 KV
__device__ __half g_AOh[ROWS * DIM];          // fp16 attention output
__device__ __half g_Xh [ROWS * DIM];          // fp16 x
__device__ __half g_Ch [ROWS * DIM];          // fp16 context
// pre-transposed fp16 weights: Wt[n][k]
__device__ __half g_WtQh [DIM * DIM];
__device__ __half g_WtKVh[2 * DIM * DIM];
__device__ __half g_WtOh [DIM * DIM];

// ---------------- GEMM tiling ----------------
#define BM 128
#define BN 128
#define BK 64                       // 64 fp16 = 128B rows
#define NKT (DIM / BK)              // 8
#define STAGES 3
#define W_STAGE 16384
#define X_STAGE 16384
#define STAGE_BYTES (W_STAGE + X_STAGE)
#define SMEM_BYTES (STAGES * STAGE_BYTES)   // 98304 -> 2 CTA/SM

// ---------------- helpers ----------------
__device__ __forceinline__ uint32_t smem_u32(const void* p) {
    uint32_t a;
    asm("{ .reg .u64 t; cvta.to.shared.u64 t, %1; cvt.u32.u64 %0, t; }"
        : "=r"(a) : "l"(p));
    return a;
}
__device__ __forceinline__ void cp16(uint32_t dst, const void* src) {
    asm volatile("cp.async.cg.shared.global [%0], [%1], 16;"
                 :: "r"(dst), "l"(src));
}
__device__ __forceinline__ void cp_commit() {
    asm volatile("cp.async.commit_group;");
}
template <int N>
__device__ __forceinline__ void cp_wait() {
    asm volatile("cp.async.wait_group %0;" :: "n"(N));
}
#define LDSM4(r0, r1, r2, r3, a) \
    asm volatile("ldmatrix.sync.aligned.m8n8.x4.shared.b16 {%0,%1,%2,%3}, [%4];" \
        : "=r"(r0), "=r"(r1), "=r"(r2), "=r"(r3) : "r"(a))

__device__ __forceinline__ void mma_f16(
    float c[4], uint32_t a0, uint32_t a1, uint32_t a2, uint32_t a3,
    uint32_t b0, uint32_t b1)
{
    asm volatile(
        "mma.sync.aligned.m16n8k16.row.col.f32.f16.f16.f32 "
        "{%0,%1,%2,%3}, {%4,%5,%6,%7}, {%8,%9}, {%0,%1,%2,%3};"
        : "+f"(c[0]), "+f"(c[1]), "+f"(c[2]), "+f"(c[3])
        : "r"(a0), "r"(a1), "r"(a2), "r"(a3), "r"(b0), "r"(b1));
}

// unpack 8 halves (uint4) -> 8 floats
__device__ __forceinline__ void cvt8(const uint4& u, float* f) {
    float2 a = __half22float2(*(const __half2*)&u.x);
    float2 b = __half22float2(*(const __half2*)&u.y);
    float2 c = __half22float2(*(const __half2*)&u.z);
    float2 d = __half22float2(*(const __half2*)&u.w);
    f[0] = a.x; f[1] = a.y; f[2] = b.x; f[3] = b.y;
    f[4] = c.x; f[5] = c.y; f[6] = d.x; f[7] = d.y;
}

// ---------------- prep: all 3 weights transposed+rounded in ONE launch ----------------
__global__ void transpose_all(const float* __restrict__ Wq,
                              const float* __restrict__ Wkv,
                              const float* __restrict__ Wo)
{
    int y = blockIdx.y;
    const float* W;
    __half* Wt;
    int N, n0;
    if (y < 16)      { W = Wq;  Wt = g_WtQh;  N = DIM;     n0 = y * 32; }
    else if (y < 48) { W = Wkv; Wt = g_WtKVh; N = 2 * DIM; n0 = (y - 16) * 32; }
    else             { W = Wo;  Wt = g_WtOh;  N = DIM;     n0 = (y - 48) * 32; }

    __shared__ float t[32][33];
    int k0 = blockIdx.x * 32;
    int tx = threadIdx.x, ty = threadIdx.y;
#pragma unroll
    for (int i = ty; i < 32; i += 8)
        t[i][tx] = W[(size_t)(k0 + i) * N + n0 + tx];
    __syncthreads();
#pragma unroll
    for (int i = ty; i < 32; i += 8)
        Wt[(size_t)(n0 + i) * DIM + k0 + tx] = __float2half_rn(t[tx][i]);
}

// ---------------- prep: x AND ctx -> fp16 in ONE launch ----------------
#define TOH_BLOCKS (ROWS * DIM / 4 / 256)     // 32768 per tensor
__global__ void to_half2(const float* __restrict__ x, const float* __restrict__ ctx)
{
    int bid = blockIdx.x;
    const float* src;
    __half* dst;
    int base;
    if (bid < TOH_BLOCKS) { src = x;   dst = g_Xh; base = bid; }
    else                  { src = ctx; dst = g_Ch; base = bid - TOH_BLOCKS; }
    int i = (base * 256 + threadIdx.x) * 4;
    float4 v = *(const float4*)&src[i];
    *(__half2*)&dst[i]     = __floats2half2_rn(v.x, v.y);
    *(__half2*)&dst[i + 2] = __floats2half2_rn(v.z, v.w);
}

// shared MMA mainloop body (one k-tile)
__device__ __forceinline__ void mma_tile(
    uint32_t sW, uint32_t sX, int nb, int mb,
    int lx7, int arow, int agb, int brow, int bgb,
    float acc[2][8][4])
{
#pragma unroll
    for (int ks = 0; ks < 4; ks++) {
        uint32_t aw[2][4];
#pragma unroll
        for (int inf = 0; inf < 2; inf++) {
            int row = nb + inf * 16 + arow;
            uint32_t ad = sW + row * 128
                        + (uint32_t)(((2 * ks + agb) ^ lx7) << 4);
            LDSM4(aw[inf][0], aw[inf][1], aw[inf][2], aw[inf][3], ad);
        }
        uint32_t bx[8][2];
#pragma unroll
        for (int jp = 0; jp < 4; jp++) {
            int row = mb + jp * 16 + brow;
            uint32_t ad = sX + row * 128
                        + (uint32_t)(((2 * ks + bgb) ^ lx7) << 4);
            uint32_t r0, r1, r2, r3;
            LDSM4(r0, r1, r2, r3, ad);
            bx[2 * jp][0]     = r0;
            bx[2 * jp][1]     = r1;
            bx[2 * jp + 1][0] = r2;
            bx[2 * jp + 1][1] = r3;
        }
#pragma unroll
        for (int inf = 0; inf < 2; inf++)
#pragma unroll
            for (int jm = 0; jm < 8; jm++)
                mma_f16(acc[inf][jm],
                        aw[inf][0], aw[inf][1], aw[inf][2], aw[inf][3],
                        bx[jm][0], bx[jm][1]);
    }
}

// ---------------- fused Q+KV GEMM (fp16 in, fp16 out) ----------------
// grid.x: 0..3 -> Q n-tiles (Xh @ WtQ), 4..11 -> KV n-tiles (Ch @ WtKV)
__global__ __launch_bounds__(256, 2) void gemm_qkv(
    const float* __restrict__ bq, const float* __restrict__ bkv)
{
    extern __shared__ float smf[];
    const uint32_t smb = smem_u32(smf);

    const int nt = blockIdx.x;
    const int isKV = (nt >= 4);
    const __half* Act  = isKV ? g_Ch : g_Xh;
    const __half* Wt   = isKV ? g_WtKVh : g_WtQh;
    const float* bias  = isKV ? bkv : bq;
    __half* Co         = isKV ? g_KVh : g_Qh;
    const int ldN      = isKV ? 2 * DIM : DIM;
    const int n0       = (isKV ? nt - 4 : nt) * BN;
    const int m0       = blockIdx.y * BM;

    const int tid = threadIdx.x;
    const int wid = tid >> 5;
    const int l   = tid & 31;
    const int nb = (wid & 3) * 32, mb = (wid >> 2) * 64;

    const int lx7  = l & 7;
    const int arow = (l & 7) + ((l >> 3) & 1) * 8;
    const int agb  = l >> 4;
    const int brow = (l & 7) + ((l >> 4) << 3);
    const int bgb  = (l >> 3) & 1;

    float acc[2][8][4];
#pragma unroll
    for (int i = 0; i < 2; i++)
#pragma unroll
        for (int j = 0; j < 8; j++)
#pragma unroll
            for (int c = 0; c < 4; c++) acc[i][j][c] = 0.0f;

    auto issue = [&](int t) {
        uint32_t sW = smb + (t % STAGES) * STAGE_BYTES;
        uint32_t sX = sW + W_STAGE;
#pragma unroll
        for (int j = 0; j < 4; j++) {
            int g = tid + j * 256;
            int r = g >> 3, c = g & 7;
            uint32_t off = (uint32_t)(r * 128 + ((c ^ (r & 7)) << 4));
            cp16(sW + off, &Wt[(size_t)(n0 + r) * DIM + t * BK + c * 8]);
            cp16(sX + off, &Act[(size_t)(m0 + r) * DIM + t * BK + c * 8]);
        }
    };

    issue(0); cp_commit();
    issue(1); cp_commit();

    for (int kt = 0; kt < NKT; kt++) {
        cp_wait<STAGES - 2>();
        __syncthreads();
        if (kt + STAGES - 1 < NKT) issue(kt + STAGES - 1);
        cp_commit();
        uint32_t sW = smb + (kt % STAGES) * STAGE_BYTES;
        mma_tile(sW, sW + W_STAGE, nb, mb, lx7, arow, agb, brow, bgb, acc);
    }

    // epilogue: transpose via smem, bias, fp16 coalesced store
    cp_wait<0>();
    __syncthreads();
    float* Cs = smf;
    const int gq = l >> 2, tq = l & 3;
#pragma unroll
    for (int inf = 0; inf < 2; inf++) {
        int nn = nb + inf * 16 + gq;
#pragma unroll
        for (int jm = 0; jm < 8; jm++) {
            int mm = mb + jm * 8 + 2 * tq;
            Cs[mm * 132 + nn]           = acc[inf][jm][0];
            Cs[(mm + 1) * 132 + nn]     = acc[inf][jm][1];
            Cs[mm * 132 + nn + 8]       = acc[inf][jm][2];
            Cs[(mm + 1) * 132 + nn + 8] = acc[inf][jm][3];
        }
    }
    __syncthreads();
#pragma unroll
    for (int it = 0; it < 8; it++) {
        int idx = tid + it * 256;
        int r = idx >> 4, c = (idx & 15) * 8;
        float4 v0 = *(float4*)&Cs[r * 132 + c];
        float4 v1 = *(float4*)&Cs[r * 132 + c + 4];
        const float* bp = &bias[n0 + c];
        __half2 h[4];
        h[0] = __floats2half2_rn(v0.x + bp[0], v0.y + bp[1]);
        h[1] = __floats2half2_rn(v0.z + bp[2], v0.w + bp[3]);
        h[2] = __floats2half2_rn(v1.x + bp[4], v1.y + bp[5]);
        h[3] = __floats2half2_rn(v1.z + bp[6], v1.w + bp[7]);
        *(uint4*)&Co[(size_t)(m0 + r) * ldN + n0 + c] = *(uint4*)h;
    }
}

// ---------------- O GEMM: fp16 AO in, fp32 out ----------------
__global__ __launch_bounds__(256, 2) void gemm_o(
    const float* __restrict__ bias, float* __restrict__ Cext, int ldN)
{
    extern __shared__ float smf[];
    const uint32_t smb = smem_u32(smf);

    const __half* Act = g_AOh;
    const __half* Wt  = g_WtOh;

    const int tid = threadIdx.x;
    const int wid = tid >> 5;
    const int l   = tid & 31;
    const int nb = (wid & 3) * 32, mb = (wid >> 2) * 64;
    const int m0 = blockIdx.y * BM, n0 = blockIdx.x * BN;

    const int lx7  = l & 7;
    const int arow = (l & 7) + ((l >> 3) & 1) * 8;
    const int agb  = l >> 4;
    const int brow = (l & 7) + ((l >> 4) << 3);
    const int bgb  = (l >> 3) & 1;

    float acc[2][8][4];
#pragma unroll
    for (int i = 0; i < 2; i++)
#pragma unroll
        for (int j = 0; j < 8; j++)
#pragma unroll
            for (int c = 0; c < 4; c++) acc[i][j][c] = 0.0f;

    auto issue = [&](int t) {
        uint32_t sW = smb + (t % STAGES) * STAGE_BYTES;
        uint32_t sX = sW + W_STAGE;
#pragma unroll
        for (int j = 0; j < 4; j++) {
            int g = tid + j * 256;
            int r = g >> 3, c = g & 7;
            uint32_t off = (uint32_t)(r * 128 + ((c ^ (r & 7)) << 4));
            cp16(sW + off, &Wt[(size_t)(n0 + r) * DIM + t * BK + c * 8]);
            cp16(sX + off, &Act[(size_t)(m0 + r) * DIM + t * BK + c * 8]);
        }
    };

    issue(0); cp_commit();
    issue(1); cp_commit();

    for (int kt = 0; kt < NKT; kt++) {
        cp_wait<STAGES - 2>();
        __syncthreads();
        if (kt + STAGES - 1 < NKT) issue(kt + STAGES - 1);
        cp_commit();
        uint32_t sW = smb + (kt % STAGES) * STAGE_BYTES;
        mma_tile(sW, sW + W_STAGE, nb, mb, lx7, arow, agb, brow, bgb, acc);
    }

    cp_wait<0>();
    __syncthreads();
    float* Cs = smf;
    const int gq = l >> 2, tq = l & 3;
#pragma unroll
    for (int inf = 0; inf < 2; inf++) {
        int nn = nb + inf * 16 + gq;
#pragma unroll
        for (int jm = 0; jm < 8; jm++) {
            int mm = mb + jm * 8 + 2 * tq;
            Cs[mm * 132 + nn]           = acc[inf][jm][0];
            Cs[(mm + 1) * 132 + nn]     = acc[inf][jm][1];
            Cs[mm * 132 + nn + 8]       = acc[inf][jm][2];
            Cs[(mm + 1) * 132 + nn + 8] = acc[inf][jm][3];
        }
    }
    __syncthreads();
#pragma unroll
    for (int it = 0; it < 16; it++) {
        int idx = tid + it * 256;
        int r = idx >> 5, c = (idx & 31) * 4;
        float4 v = *(float4*)&Cs[r * 132 + c];
        v.x += bias[n0 + c];
        v.y += bias[n0 + c + 1];
        v.z += bias[n0 + c + 2];
        v.w += bias[n0 + c + 3];
        *(float4*)&Cext[(size_t)(m0 + r) * ldN + n0 + c] = v;
    }
}

// ---------------- attention v2: 8 lanes per (b,h), 4 per warp ----------------
// lane g (0..7) of a group owns head-dims [8g, 8g+8).
__global__ __launch_bounds__(256) void attn_kernel()
{
    const int wid = threadIdx.x >> 5;
    const int lane = threadIdx.x & 31;
    const int grp = lane >> 3;       // 0..3
    const int g   = lane & 7;        // 0..7
    const int bh  = (blockIdx.x * 8 + wid) * 4 + grp;
    const int b = bh >> 3, h = bh & 7;

    const __half* qb  = g_Qh  + (size_t)b * SEQ * DIM       + h * 64 + g * 8;
    const __half* kvb = g_KVh + (size_t)b * SEQ * (2 * DIM) + h * 64 + g * 8;

    uint4 kh[4], vh[4];
    float qf[4][8];
#pragma unroll
    for (int i = 0; i < 4; i++) {
        uint4 qh = *(const uint4*)&qb[i * DIM];
        kh[i] = *(const uint4*)&kvb[i * (2 * DIM)];
        vh[i] = *(const uint4*)&kvb[i * (2 * DIM) + DIM];
        cvt8(qh, qf[i]);
    }

    // scores: partial dot over this lane's 8 dims
    float s[4][4];
#pragma unroll
    for (int j = 0; j < 4; j++) {
        float kf[8];
        cvt8(kh[j], kf);
#pragma unroll
        for (int i = 0; i < 4; i++) {
            float a = qf[i][0] * kf[0];
#pragma unroll
            for (int d = 1; d < 8; d++) a = fmaf(qf[i][d], kf[d], a);
            s[i][j] = a;
        }
    }
    // reduce over the 8-lane group (3 stages; serves all 4 groups per shuffle)
#pragma unroll
    for (int i = 0; i < 4; i++)
#pragma unroll
        for (int j = 0; j < 4; j++)
#pragma unroll
            for (int o = 4; o > 0; o >>= 1)
                s[i][j] += __shfl_xor_sync(0xFFFFFFFFu, s[i][j], o);

    // softmax (redundant across the 8 lanes of a group; lane-local data)
    float p[4][4];
#pragma unroll
    for (int i = 0; i < 4; i++) {
        const int jm = 3 - i;                       // masked pair (dist = sqrt2)
#pragma unroll
        for (int j = 0; j < 4; j++) s[i][j] *= SCALE_F;
        s[i][jm] = -(float)(jm + 1) * GAMMA_F;      // finite bias, in denominator

        float mx = fmaxf(fmaxf(s[i][0], s[i][1]), fmaxf(s[i][2], s[i][3]));
        float e0 = __expf(s[i][0] - mx), e1 = __expf(s[i][1] - mx);
        float e2 = __expf(s[i][2] - mx), e3 = __expf(s[i][3] - mx);
        float inv = 1.0f / (e0 + e1 + e2 + e3);
        p[i][0] = e0 * inv; p[i][1] = e1 * inv;
        p[i][2] = e2 * inv; p[i][3] = e3 * inv;
        p[i][jm] = 0.0f;                            // post-softmax mask
    }

    // out = P @ V over this lane's 8 dims
    float of[4][8];
#pragma unroll
    for (int i = 0; i < 4; i++)
#pragma unroll
        for (int d = 0; d < 8; d++) of[i][d] = 0.0f;
#pragma unroll
    for (int j = 0; j < 4; j++) {
        float vf[8];
        cvt8(vh[j], vf);
#pragma unroll
        for (int i = 0; i < 4; i++)
#pragma unroll
            for (int d = 0; d < 8; d++)
                of[i][d] = fmaf(p[i][j], vf[d], of[i][d]);
    }

    __half* dst = g_AOh + (size_t)b * SEQ * DIM + h * 64 + g * 8;
#pragma unroll
    for (int i = 0; i < 4; i++) {
        __half2 hh[4];
        hh[0] = __floats2half2_rn(of[i][0], of[i][1]);
        hh[1] = __floats2half2_rn(of[i][2], of[i][3]);
        hh[2] = __floats2half2_rn(of[i][4], of[i][5]);
        hh[3] = __floats2half2_rn(of[i][6], of[i][7]);
        *(uint4*)&dst[i * DIM] = *(uint4*)hh;
    }
}

// ---------------- launch ----------------
extern "C" void kernel_launch(void* const* d_in, const int* in_sizes, int n_in,
                              void* d_out, int out_size)
{
    const float* x   = (const float*)d_in[0];
    const float* ctx = (const float*)d_in[1];
    const float* Wq  = (const float*)d_in[2];
    const float* bq  = (const float*)d_in[3];
    const float* Wkv = (const float*)d_in[4];
    const float* bkv = (const float*)d_in[5];
    const float* Wo  = (const float*)d_in[6];
    const float* bo  = (const float*)d_in[7];
    float* out = (float*)d_out;

    cudaFuncSetAttribute(gemm_qkv, cudaFuncAttributeMaxDynamicSharedMemorySize, SMEM_BYTES);
    cudaFuncSetAttribute(gemm_o, cudaFuncAttributeMaxDynamicSharedMemorySize, SMEM_BYTES);

    // prep: all weights in one launch; both activations in one launch
    transpose_all<<<dim3(16, 64), dim3(32, 8)>>>(Wq, Wkv, Wo);
    to_half2<<<2 * TOH_BLOCKS, 256>>>(x, ctx);

    // Q and KV in one launch (fp16 in/out)
    gemm_qkv<<<dim3(12, ROWS / BM), 256, SMEM_BYTES>>>(bq, bkv);
    // attention: 32 (b,h) per block -> 4096 blocks
    attn_kernel<<<BATCH * HEADS / 32, 256>>>();
    // out = AO @ Wo + bo (fp32 out)
    gemm_o<<<dim3(DIM / BN, ROWS / BM), 256, SMEM_BYTES>>>(bo, out, DIM);
}

// round 12
// speedup vs baseline: 1.2857x; 1.1154x over previous
#include <cuda_runtime.h>
#include <cuda_fp16.h>
#include <cstdint>

// ---------------- problem constants ----------------
#define BATCH   16384
#define SEQ     4
#define DIM     512
#define ROWS    (BATCH * SEQ)      // 65536
#define HEADS   8
#define GAMMA_F 0.4f
#define SCALE_F 0.044194173824159216f  // 512^-0.5

// scratch (allocation-free rule)
__device__ __half g_Qh [ROWS * DIM];          // fp16 Q
__device__ __half g_KVh[ROWS * 2 * DIM];      // fp16 KV
__device__ __half g_AOh[ROWS * DIM];          // fp16 attention output
__device__ __half g_Xh [ROWS * DIM];          // fp16 x
__device__ __half g_Ch [ROWS * DIM];          // fp16 context
// pre-transposed fp16 weights: Wt[n][k]
__device__ __half g_WtQh [DIM * DIM];
__device__ __half g_WtKVh[2 * DIM * DIM];
__device__ __half g_WtOh [DIM * DIM];

// ---------------- GEMM tiling ----------------
#define BM 128
#define BN 128
#define BK 64                       // 64 fp16 = 128B rows
#define NKT (DIM / BK)              // 8
#define STAGES 3
#define W_STAGE 16384
#define X_STAGE 16384
#define STAGE_BYTES (W_STAGE + X_STAGE)
#define SMEM_BYTES (STAGES * STAGE_BYTES)   // 98304 -> 2 CTA/SM

// ---------------- helpers ----------------
__device__ __forceinline__ uint32_t smem_u32(const void* p) {
    uint32_t a;
    asm("{ .reg .u64 t; cvta.to.shared.u64 t, %1; cvt.u32.u64 %0, t; }"
        : "=r"(a) : "l"(p));
    return a;
}
__device__ __forceinline__ void cp16(uint32_t dst, const void* src) {
    asm volatile("cp.async.cg.shared.global [%0], [%1], 16;"
                 :: "r"(dst), "l"(src));
}
__device__ __forceinline__ void cp_commit() {
    asm volatile("cp.async.commit_group;");
}
template <int N>
__device__ __forceinline__ void cp_wait() {
    asm volatile("cp.async.wait_group %0;" :: "n"(N));
}
#define LDSM4(r0, r1, r2, r3, a) \
    asm volatile("ldmatrix.sync.aligned.m8n8.x4.shared.b16 {%0,%1,%2,%3}, [%4];" \
        : "=r"(r0), "=r"(r1), "=r"(r2), "=r"(r3) : "r"(a))

__device__ __forceinline__ void mma_f16(
    float c[4], uint32_t a0, uint32_t a1, uint32_t a2, uint32_t a3,
    uint32_t b0, uint32_t b1)
{
    asm volatile(
        "mma.sync.aligned.m16n8k16.row.col.f32.f16.f16.f32 "
        "{%0,%1,%2,%3}, {%4,%5,%6,%7}, {%8,%9}, {%0,%1,%2,%3};"
        : "+f"(c[0]), "+f"(c[1]), "+f"(c[2]), "+f"(c[3])
        : "r"(a0), "r"(a1), "r"(a2), "r"(a3), "r"(b0), "r"(b1));
}

// unpack 8 halves (uint4) -> 8 floats
__device__ __forceinline__ void cvt8(const uint4& u, float* f) {
    float2 a = __half22float2(*(const __half2*)&u.x);
    float2 b = __half22float2(*(const __half2*)&u.y);
    float2 c = __half22float2(*(const __half2*)&u.z);
    float2 d = __half22float2(*(const __half2*)&u.w);
    f[0] = a.x; f[1] = a.y; f[2] = b.x; f[3] = b.y;
    f[4] = c.x; f[5] = c.y; f[6] = d.x; f[7] = d.y;
}

// ---------------- prep: all 3 weights transposed+rounded in ONE launch ----------------
__global__ void transpose_all(const float* __restrict__ Wq,
                              const float* __restrict__ Wkv,
                              const float* __restrict__ Wo)
{
    int y = blockIdx.y;
    const float* W;
    __half* Wt;
    int N, n0;
    if (y < 16)      { W = Wq;  Wt = g_WtQh;  N = DIM;     n0 = y * 32; }
    else if (y < 48) { W = Wkv; Wt = g_WtKVh; N = 2 * DIM; n0 = (y - 16) * 32; }
    else             { W = Wo;  Wt = g_WtOh;  N = DIM;     n0 = (y - 48) * 32; }

    __shared__ float t[32][33];
    int k0 = blockIdx.x * 32;
    int tx = threadIdx.x, ty = threadIdx.y;
#pragma unroll
    for (int i = ty; i < 32; i += 8)
        t[i][tx] = W[(size_t)(k0 + i) * N + n0 + tx];
    __syncthreads();
#pragma unroll
    for (int i = ty; i < 32; i += 8)
        Wt[(size_t)(n0 + i) * DIM + k0 + tx] = __float2half_rn(t[tx][i]);
}

// ---------------- prep: x AND ctx -> fp16 in ONE launch ----------------
// 8 floats per thread; streaming reads (x/ctx are never read again).
#define TOH_BLOCKS (ROWS * DIM / 8 / 256)     // 16384 per tensor
__global__ void to_half2(const float* __restrict__ x, const float* __restrict__ ctx)
{
    int bid = blockIdx.x;
    const float* src;
    __half* dst;
    int base;
    if (bid < TOH_BLOCKS) { src = x;   dst = g_Xh; base = bid; }
    else                  { src = ctx; dst = g_Ch; base = bid - TOH_BLOCKS; }
    int i = (base * 256 + threadIdx.x) * 8;
    float4 v0 = __ldcs((const float4*)&src[i]);
    float4 v1 = __ldcs((const float4*)&src[i + 4]);
    __half2 h[4];
    h[0] = __floats2half2_rn(v0.x, v0.y);
    h[1] = __floats2half2_rn(v0.z, v0.w);
    h[2] = __floats2half2_rn(v1.x, v1.y);
    h[3] = __floats2half2_rn(v1.z, v1.w);
    *(uint4*)&dst[i] = *(uint4*)h;
}

// shared MMA mainloop body (one k-tile)
__device__ __forceinline__ void mma_tile(
    uint32_t sW, uint32_t sX, int nb, int mb,
    int lx7, int arow, int agb, int brow, int bgb,
    float acc[2][8][4])
{
#pragma unroll
    for (int ks = 0; ks < 4; ks++) {
        uint32_t aw[2][4];
#pragma unroll
        for (int inf = 0; inf < 2; inf++) {
            int row = nb + inf * 16 + arow;
            uint32_t ad = sW + row * 128
                        + (uint32_t)(((2 * ks + agb) ^ lx7) << 4);
            LDSM4(aw[inf][0], aw[inf][1], aw[inf][2], aw[inf][3], ad);
        }
        uint32_t bx[8][2];
#pragma unroll
        for (int jp = 0; jp < 4; jp++) {
            int row = mb + jp * 16 + brow;
            uint32_t ad = sX + row * 128
                        + (uint32_t)(((2 * ks + bgb) ^ lx7) << 4);
            uint32_t r0, r1, r2, r3;
            LDSM4(r0, r1, r2, r3, ad);
            bx[2 * jp][0]     = r0;
            bx[2 * jp][1]     = r1;
            bx[2 * jp + 1][0] = r2;
            bx[2 * jp + 1][1] = r3;
        }
#pragma unroll
        for (int inf = 0; inf < 2; inf++)
#pragma unroll
            for (int jm = 0; jm < 8; jm++)
                mma_f16(acc[inf][jm],
                        aw[inf][0], aw[inf][1], aw[inf][2], aw[inf][3],
                        bx[jm][0], bx[jm][1]);
    }
}

// ---------------- fused Q+KV GEMM (fp16 in, fp16 out) ----------------
// grid.x: 0..3 -> Q n-tiles (Xh @ WtQ), 4..11 -> KV n-tiles (Ch @ WtKV)
__global__ __launch_bounds__(256, 2) void gemm_qkv(
    const float* __restrict__ bq, const float* __restrict__ bkv)
{
    extern __shared__ float smf[];
    const uint32_t smb = smem_u32(smf);

    const int nt = blockIdx.x;
    const int isKV = (nt >= 4);
    const __half* Act  = isKV ? g_Ch : g_Xh;
    const __half* Wt   = isKV ? g_WtKVh : g_WtQh;
    const float* bias  = isKV ? bkv : bq;
    __half* Co         = isKV ? g_KVh : g_Qh;
    const int ldN      = isKV ? 2 * DIM : DIM;
    const int n0       = (isKV ? nt - 4 : nt) * BN;
    const int m0       = blockIdx.y * BM;

    const int tid = threadIdx.x;
    const int wid = tid >> 5;
    const int l   = tid & 31;
    const int nb = (wid & 3) * 32, mb = (wid >> 2) * 64;

    const int lx7  = l & 7;
    const int arow = (l & 7) + ((l >> 3) & 1) * 8;
    const int agb  = l >> 4;
    const int brow = (l & 7) + ((l >> 4) << 3);
    const int bgb  = (l >> 3) & 1;

    float acc[2][8][4];
#pragma unroll
    for (int i = 0; i < 2; i++)
#pragma unroll
        for (int j = 0; j < 8; j++)
#pragma unroll
            for (int c = 0; c < 4; c++) acc[i][j][c] = 0.0f;

    // per-thread copy coords (compile-time invariant)
    const int cr = tid >> 3, cc = tid & 7;
    const uint32_t coff = (uint32_t)(cr * 128 + ((cc ^ (cr & 7)) << 4));
    const __half* wsrc = &Wt[(size_t)(n0 + cr) * DIM + cc * 8];
    const __half* xsrc = &Act[(size_t)(m0 + cr) * DIM + cc * 8];

#define QKV_ISSUE(T) do {                                                   \
        uint32_t sW_ = smb + ((T) % STAGES) * STAGE_BYTES;                  \
        uint32_t sX_ = sW_ + W_STAGE;                                       \
        _Pragma("unroll")                                                   \
        for (int j = 0; j < 4; j++) {                                       \
            uint32_t o_ = coff + (uint32_t)(j * 32 * 128);                  \
            cp16(sW_ + o_, wsrc + (size_t)(j * 32) * DIM + (T) * BK);       \
            cp16(sX_ + o_, xsrc + (size_t)(j * 32) * DIM + (T) * BK);       \
        }                                                                   \
    } while (0)

    QKV_ISSUE(0); cp_commit();
    QKV_ISSUE(1); cp_commit();

#pragma unroll
    for (int kt = 0; kt < NKT; kt++) {
        cp_wait<STAGES - 2>();
        __syncthreads();
        if (kt + STAGES - 1 < NKT) QKV_ISSUE(kt + STAGES - 1);
        cp_commit();
        uint32_t sW = smb + (kt % STAGES) * STAGE_BYTES;
        mma_tile(sW, sW + W_STAGE, nb, mb, lx7, arow, agb, brow, bgb, acc);
    }
#undef QKV_ISSUE

    // epilogue: transpose via smem, bias, fp16 coalesced store
    cp_wait<0>();
    __syncthreads();
    float* Cs = smf;
    const int gq = l >> 2, tq = l & 3;
#pragma unroll
    for (int inf = 0; inf < 2; inf++) {
        int nn = nb + inf * 16 + gq;
#pragma unroll
        for (int jm = 0; jm < 8; jm++) {
            int mm = mb + jm * 8 + 2 * tq;
            Cs[mm * 132 + nn]           = acc[inf][jm][0];
            Cs[(mm + 1) * 132 + nn]     = acc[inf][jm][1];
            Cs[mm * 132 + nn + 8]       = acc[inf][jm][2];
            Cs[(mm + 1) * 132 + nn + 8] = acc[inf][jm][3];
        }
    }
    __syncthreads();
#pragma unroll
    for (int it = 0; it < 8; it++) {
        int idx = tid + it * 256;
        int r = idx >> 4, c = (idx & 15) * 8;
        float4 v0 = *(float4*)&Cs[r * 132 + c];
        float4 v1 = *(float4*)&Cs[r * 132 + c + 4];
        const float* bp = &bias[n0 + c];
        __half2 h[4];
        h[0] = __floats2half2_rn(v0.x + bp[0], v0.y + bp[1]);
        h[1] = __floats2half2_rn(v0.z + bp[2], v0.w + bp[3]);
        h[2] = __floats2half2_rn(v1.x + bp[4], v1.y + bp[5]);
        h[3] = __floats2half2_rn(v1.z + bp[6], v1.w + bp[7]);
        *(uint4*)&Co[(size_t)(m0 + r) * ldN + n0 + c] = *(uint4*)h;
    }
}

// ---------------- O GEMM: fp16 AO in, fp32 out ----------------
__global__ __launch_bounds__(256, 2) void gemm_o(
    const float* __restrict__ bias, float* __restrict__ Cext, int ldN)
{
    extern __shared__ float smf[];
    const uint32_t smb = smem_u32(smf);

    const int tid = threadIdx.x;
    const int wid = tid >> 5;
    const int l   = tid & 31;
    const int nb = (wid & 3) * 32, mb = (wid >> 2) * 64;
    const int m0 = blockIdx.y * BM, n0 = blockIdx.x * BN;

    const int lx7  = l & 7;
    const int arow = (l & 7) + ((l >> 3) & 1) * 8;
    const int agb  = l >> 4;
    const int brow = (l & 7) + ((l >> 4) << 3);
    const int bgb  = (l >> 3) & 1;

    float acc[2][8][4];
#pragma unroll
    for (int i = 0; i < 2; i++)
#pragma unroll
        for (int j = 0; j < 8; j++)
#pragma unroll
            for (int c = 0; c < 4; c++) acc[i][j][c] = 0.0f;

    const int cr = tid >> 3, cc = tid & 7;
    const uint32_t coff = (uint32_t)(cr * 128 + ((cc ^ (cr & 7)) << 4));
    const __half* wsrc = &g_WtOh[(size_t)(n0 + cr) * DIM + cc * 8];
    const __half* xsrc = &g_AOh[(size_t)(m0 + cr) * DIM + cc * 8];

#define O_ISSUE(T) do {                                                     \
        uint32_t sW_ = smb + ((T) % STAGES) * STAGE_BYTES;                  \
        uint32_t sX_ = sW_ + W_STAGE;                                       \
        _Pragma("unroll")                                                   \
        for (int j = 0; j < 4; j++) {                                       \
            uint32_t o_ = coff + (uint32_t)(j * 32 * 128);                  \
            cp16(sW_ + o_, wsrc + (size_t)(j * 32) * DIM + (T) * BK);       \
            cp16(sX_ + o_, xsrc + (size_t)(j * 32) * DIM + (T) * BK);       \
        }                                                                   \
    } while (0)

    O_ISSUE(0); cp_commit();
    O_ISSUE(1); cp_commit();

#pragma unroll
    for (int kt = 0; kt < NKT; kt++) {
        cp_wait<STAGES - 2>();
        __syncthreads();
        if (kt + STAGES - 1 < NKT) O_ISSUE(kt + STAGES - 1);
        cp_commit();
        uint32_t sW = smb + (kt % STAGES) * STAGE_BYTES;
        mma_tile(sW, sW + W_STAGE, nb, mb, lx7, arow, agb, brow, bgb, acc);
    }
#undef O_ISSUE

    cp_wait<0>();
    __syncthreads();
    float* Cs = smf;
    const int gq = l >> 2, tq = l & 3;
#pragma unroll
    for (int inf = 0; inf < 2; inf++) {
        int nn = nb + inf * 16 + gq;
#pragma unroll
        for (int jm = 0; jm < 8; jm++) {
            int mm = mb + jm * 8 + 2 * tq;
            Cs[mm * 132 + nn]           = acc[inf][jm][0];
            Cs[(mm + 1) * 132 + nn]     = acc[inf][jm][1];
            Cs[mm * 132 + nn + 8]       = acc[inf][jm][2];
            Cs[(mm + 1) * 132 + nn + 8] = acc[inf][jm][3];
        }
    }
    __syncthreads();
#pragma unroll
    for (int it = 0; it < 16; it++) {
        int idx = tid + it * 256;
        int r = idx >> 5, c = (idx & 31) * 4;
        float4 v = *(float4*)&Cs[r * 132 + c];
        v.x += bias[n0 + c];
        v.y += bias[n0 + c + 1];
        v.z += bias[n0 + c + 2];
        v.w += bias[n0 + c + 3];
        *(float4*)&Cext[(size_t)(m0 + r) * ldN + n0 + c] = v;
    }
}

// ---------------- attention: 8 lanes per (b,h), 4 per warp ----------------
__global__ __launch_bounds__(256) void attn_kernel()
{
    const int wid = threadIdx.x >> 5;
    const int lane = threadIdx.x & 31;
    const int grp = lane >> 3;       // 0..3
    const int g   = lane & 7;        // 0..7
    const int bh  = (blockIdx.x * 8 + wid) * 4 + grp;
    const int b = bh >> 3, h = bh & 7;

    const __half* qb  = g_Qh  + (size_t)b * SEQ * DIM       + h * 64 + g * 8;
    const __half* kvb = g_KVh + (size_t)b * SEQ * (2 * DIM) + h * 64 + g * 8;

    uint4 kh[4], vh[4];
    float qf[4][8];
#pragma unroll
    for (int i = 0; i < 4; i++) {
        uint4 qh = *(const uint4*)&qb[i * DIM];
        kh[i] = *(const uint4*)&kvb[i * (2 * DIM)];
        vh[i] = *(const uint4*)&kvb[i * (2 * DIM) + DIM];
        cvt8(qh, qf[i]);
    }

    float s[4][4];
#pragma unroll
    for (int j = 0; j < 4; j++) {
        float kf[8];
        cvt8(kh[j], kf);
#pragma unroll
        for (int i = 0; i < 4; i++) {
            float a = qf[i][0] * kf[0];
#pragma unroll
            for (int d = 1; d < 8; d++) a = fmaf(qf[i][d], kf[d], a);
            s[i][j] = a;
        }
    }
#pragma unroll
    for (int i = 0; i < 4; i++)
#pragma unroll
        for (int j = 0; j < 4; j++)
#pragma unroll
            for (int o = 4; o > 0; o >>= 1)
                s[i][j] += __shfl_xor_sync(0xFFFFFFFFu, s[i][j], o);

    float p[4][4];
#pragma unroll
    for (int i = 0; i < 4; i++) {
        const int jm = 3 - i;                       // masked pair (dist = sqrt2)
#pragma unroll
        for (int j = 0; j < 4; j++) s[i][j] *= SCALE_F;
        s[i][jm] = -(float)(jm + 1) * GAMMA_F;      // finite bias, in denominator

        float mx = fmaxf(fmaxf(s[i][0], s[i][1]), fmaxf(s[i][2], s[i][3]));
        float e0 = __expf(s[i][0] - mx), e1 = __expf(s[i][1] - mx);
        float e2 = __expf(s[i][2] - mx), e3 = __expf(s[i][3] - mx);
        float inv = 1.0f / (e0 + e1 + e2 + e3);
        p[i][0] = e0 * inv; p[i][1] = e1 * inv;
        p[i][2] = e2 * inv; p[i][3] = e3 * inv;
        p[i][jm] = 0.0f;                            // post-softmax mask
    }

    float of[4][8];
#pragma unroll
    for (int i = 0; i < 4; i++)
#pragma unroll
        for (int d = 0; d < 8; d++) of[i][d] = 0.0f;
#pragma unroll
    for (int j = 0; j < 4; j++) {
        float vf[8];
        cvt8(vh[j], vf);
#pragma unroll
        for (int i = 0; i < 4; i++)
#pragma unroll
            for (int d = 0; d < 8; d++)
                of[i][d] = fmaf(p[i][j], vf[d], of[i][d]);
    }

    __half* dst = g_AOh + (size_t)b * SEQ * DIM + h * 64 + g * 8;
#pragma unroll
    for (int i = 0; i < 4; i++) {
        __half2 hh[4];
        hh[0] = __floats2half2_rn(of[i][0], of[i][1]);
        hh[1] = __floats2half2_rn(of[i][2], of[i][3]);
        hh[2] = __floats2half2_rn(of[i][4], of[i][5]);
        hh[3] = __floats2half2_rn(of[i][6], of[i][7]);
        *(uint4*)&dst[i * DIM] = *(uint4*)hh;
    }
}

// ---------------- launch ----------------
extern "C" void kernel_launch(void* const* d_in, const int* in_sizes, int n_in,
                              void* d_out, int out_size)
{
    const float* x   = (const float*)d_in[0];
    const float* ctx = (const float*)d_in[1];
    const float* Wq  = (const float*)d_in[2];
    const float* bq  = (const float*)d_in[3];
    const float* Wkv = (const float*)d_in[4];
    const float* bkv = (const float*)d_in[5];
    const float* Wo  = (const float*)d_in[6];
    const float* bo  = (const float*)d_in[7];
    float* out = (float*)d_out;

    cudaFuncSetAttribute(gemm_qkv, cudaFuncAttributeMaxDynamicSharedMemorySize, SMEM_BYTES);
    cudaFuncSetAttribute(gemm_o, cudaFuncAttributeMaxDynamicSharedMemorySize, SMEM_BYTES);

    // prep: all weights in one launch; both activations in one launch
    transpose_all<<<dim3(16, 64), dim3(32, 8)>>>(Wq, Wkv, Wo);
    to_half2<<<2 * TOH_BLOCKS, 256>>>(x, ctx);

    // Q and KV in one launch (fp16 in/out)
    gemm_qkv<<<dim3(12, ROWS / BM), 256, SMEM_BYTES>>>(bq, bkv);
    // attention: 32 (b,h) per block -> 4096 blocks
    attn_kernel<<<BATCH * HEADS / 32, 256>>>();
    // out = AO @ Wo + bo (fp32 out)
    gemm_o<<<dim3(DIM / BN, ROWS / BM), 256, SMEM_BYTES>>>(bo, out, DIM);
}